// round 1
// baseline (speedup 1.0000x reference)
#include <cuda_runtime.h>
#include <math.h>
#include <float.h>

#define BB 32
#define QQ 900
#define MM 128
#define KC 80
#define KP1 81
#define QT 4

// scratch (no allocations allowed -> __device__ globals)
__device__ float g_cost[BB * QQ * MM];      // 14.7 MB
__device__ float g_mx[BB * QQ];
__device__ float g_se[BB * QQ];
__device__ int   g_qidx[BB * MM];
__device__ int   g_midx[BB * MM];
__device__ float g_il[BB * 3];

// ---------------- kernel A: per-(b,q) softmax max + sumexp (one warp per row) ----
__global__ void k_softmax_stats(const float* __restrict__ logits) {
    int warp = (blockIdx.x * blockDim.x + threadIdx.x) >> 5;
    int lane = threadIdx.x & 31;
    if (warp >= BB * QQ) return;
    const float* row = logits + (size_t)warp * KP1;
    float mx = -FLT_MAX;
    for (int i = lane; i < KP1; i += 32) mx = fmaxf(mx, row[i]);
    for (int o = 16; o; o >>= 1) mx = fmaxf(mx, __shfl_xor_sync(0xffffffffu, mx, o));
    float s = 0.f;
    for (int i = lane; i < KP1; i += 32) s += expf(row[i] - mx);
    for (int o = 16; o; o >>= 1) s += __shfl_xor_sync(0xffffffffu, s, o);
    if (lane == 0) { g_mx[warp] = mx; g_se[warp] = s; }
}

// ---------------- kernel B: cost matrix [B,Q,M] -------------------------------
__global__ void k_cost(const float* __restrict__ logits,
                       const float* __restrict__ pboxes,
                       const float* __restrict__ tboxes,
                       const float* __restrict__ sizes,
                       const int*   __restrict__ labels) {
    int b = blockIdx.y;
    int m = threadIdx.x;                     // blockDim.x == MM
    __shared__ float tn0[MM], tn1[MM], tn2[MM], tn3[MM], tn4[MM];
    __shared__ int   tl[MM];
    float H = sizes[b * 2 + 0], W = sizes[b * 2 + 1];
    {
        const float* tb = tboxes + ((size_t)b * MM + m) * 5;
        tn0[m] = tb[0] / W; tn1[m] = tb[1] / H;
        tn2[m] = tb[2] / W; tn3[m] = tb[3] / H;
        tn4[m] = tb[4];
        tl[m] = labels[b * MM + m];
    }
    __syncthreads();
    int q0 = blockIdx.x * QT;
#pragma unroll
    for (int qq = 0; qq < QT; qq++) {
        int q = q0 + qq;
        const float* pb = pboxes + ((size_t)b * QQ + q) * 5;
        float p0 = pb[0], p1 = pb[1], p2 = pb[2], p3 = pb[3], p4 = pb[4];
        float mx = g_mx[b * QQ + q], se = g_se[b * QQ + q];
        float lg = logits[((size_t)b * QQ + q) * KP1 + tl[m]];
        float prob = expf(lg - mx) / se;
        float l1 = fabsf(p0 - tn0[m]) + fabsf(p1 - tn1[m]) +
                   fabsf(p2 - tn2[m]) + fabsf(p3 - tn3[m]);
        float ang = 1.f - cosf(p4 - tn4[m]);
        g_cost[((size_t)b * QQ + q) * MM + m] = -2.f * prob + 5.f * l1 + 2.f * ang;
    }
}

// ---------------- kernel C: greedy matching, one block per image ---------------
// Maintains per-row min over unused columns; global argmin each iteration is a
// block reduce over 900 cached values. Tie-breaks replicate flattened argmin
// (smallest q, then smallest m).
__global__ void __launch_bounds__(256, 1) k_match() {
    int b = blockIdx.x;
    int tid = threadIdx.x;
    __shared__ float rmin[QQ];
    __shared__ int   rarg[QQ];
    __shared__ unsigned char um[MM];
    __shared__ float sv[8];
    __shared__ int   si[8];
    __shared__ int   s_selm;
    const float* C = g_cost + (size_t)b * QQ * MM;

    for (int m = tid; m < MM; m += 256) um[m] = 0;
    for (int q = tid; q < QQ; q += 256) {
        const float* row = C + (size_t)q * MM;
        float bv = row[0]; int bm = 0;
#pragma unroll 4
        for (int m = 1; m < MM; m++) {
            float v = row[m];
            if (v < bv) { bv = v; bm = m; }
        }
        rmin[q] = bv; rarg[q] = bm;
    }
    __syncthreads();

    for (int it = 0; it < MM; it++) {
        // --- block argmin over rmin (smallest value, then smallest q) ---
        float bv = FLT_MAX; int bq = QQ;
        for (int q = tid; q < QQ; q += 256) {
            float v = rmin[q];
            if (v < bv) { bv = v; bq = q; }   // increasing q => strict < keeps smallest q
        }
        for (int o = 16; o; o >>= 1) {
            float vv = __shfl_down_sync(0xffffffffu, bv, o);
            int   qq = __shfl_down_sync(0xffffffffu, bq, o);
            if (vv < bv || (vv == bv && qq < bq)) { bv = vv; bq = qq; }
        }
        if ((tid & 31) == 0) { sv[tid >> 5] = bv; si[tid >> 5] = bq; }
        __syncthreads();
        if (tid == 0) {
            float fv = sv[0]; int fq = si[0];
#pragma unroll
            for (int w = 1; w < 8; w++) {
                if (sv[w] < fv || (sv[w] == fv && si[w] < fq)) { fv = sv[w]; fq = si[w]; }
            }
            int mm = rarg[fq];
            s_selm = mm;
            g_qidx[b * MM + it] = fq;
            g_midx[b * MM + it] = mm;
            um[mm] = 1;
            rmin[fq] = FLT_MAX;              // row consumed
        }
        __syncthreads();
        if (it < MM - 1) {
            int mm = s_selm;
            // rows whose cached min pointed at consumed column must rescan
            for (int q = tid; q < QQ; q += 256) {
                if (rarg[q] == mm && rmin[q] < FLT_MAX) {
                    const float* row = C + (size_t)q * MM;
                    float nbv = FLT_MAX; int nbm = -1;
                    for (int m2 = 0; m2 < MM; m2++) {
                        if (!um[m2]) {
                            float v = row[m2];
                            if (v < nbv) { nbv = v; nbm = m2; }
                        }
                    }
                    rmin[q] = nbv; rarg[q] = nbm;
                }
            }
            __syncthreads();
        }
    }
}

// ---------------- kernel D: per-image losses -----------------------------------
__device__ __forceinline__ float block_sum256(float v, float* buf) {
    int tid = threadIdx.x;
    buf[tid] = v;
    __syncthreads();
    for (int s = 128; s > 0; s >>= 1) {
        if (tid < s) buf[tid] += buf[tid + s];
        __syncthreads();
    }
    float r = buf[0];
    __syncthreads();
    return r;
}

__global__ void k_loss(const float* __restrict__ logits,
                       const float* __restrict__ pboxes,
                       const float* __restrict__ tboxes,
                       const float* __restrict__ sizes,
                       const int*   __restrict__ labels) {
    int b = blockIdx.x;
    int tid = threadIdx.x;                    // 256
    __shared__ int   mlab[QQ];
    __shared__ float buf[256];

    for (int q = tid; q < QQ; q += 256) mlab[q] = -1;
    __syncthreads();
    if (tid < MM) {
        int q = g_qidx[b * MM + tid];
        int m = g_midx[b * MM + tid];
        mlab[q] = labels[b * MM + m];
    }
    __syncthreads();

    float H = sizes[b * 2 + 0], W = sizes[b * 2 + 1];

    float sb = 0.f, sa = 0.f;
    if (tid < MM) {
        int q = g_qidx[b * MM + tid];
        int m = g_midx[b * MM + tid];
        const float* pb = pboxes + ((size_t)b * QQ + q) * 5;
        const float* tb = tboxes + ((size_t)b * MM + m) * 5;
        float n0 = tb[0] / W, n1 = tb[1] / H, n2 = tb[2] / W, n3 = tb[3] / H;
        sb = fabsf(pb[0] - n0) + fabsf(pb[1] - n1) +
             fabsf(pb[2] - n2) + fabsf(pb[3] - n3);
        sa = 1.f - cosf(pb[4] - tb[4]);
    }

    float num = 0.f, den = 0.f;
    for (int q = tid; q < QQ; q += 256) {
        int c = mlab[q];
        float w;
        if (c < 0) { c = KC; w = 0.1f; } else { w = 1.f; }
        float lg = logits[((size_t)b * QQ + q) * KP1 + c];
        float nll = -(lg - g_mx[b * QQ + q] - logf(g_se[b * QQ + q]));
        num += w * nll;
        den += w;
    }

    float sb_t  = block_sum256(sb, buf);
    float sa_t  = block_sum256(sa, buf);
    float num_t = block_sum256(num, buf);
    float den_t = block_sum256(den, buf);

    if (tid == 0) {
        g_il[b * 3 + 0] = num_t / den_t;
        g_il[b * 3 + 1] = sb_t / (float)(MM * 4) * 5.f;
        g_il[b * 3 + 2] = sa_t / (float)MM * 2.f;
    }
}

// ---------------- kernel E: batch mean -> 4 outputs ----------------------------
__global__ void k_final(float* __restrict__ out) {
    int b = threadIdx.x;                      // 32 threads
    float lc = g_il[b * 3 + 0];
    float lb = g_il[b * 3 + 1];
    float la = g_il[b * 3 + 2];
    for (int o = 16; o; o >>= 1) {
        lc += __shfl_xor_sync(0xffffffffu, lc, o);
        lb += __shfl_xor_sync(0xffffffffu, lb, o);
        la += __shfl_xor_sync(0xffffffffu, la, o);
    }
    if (b == 0) {
        lc /= (float)BB; lb /= (float)BB; la /= (float)BB;
        out[0] = lc;
        out[1] = lb;
        out[2] = la;
        out[3] = lc + lb + la;
    }
}

extern "C" void kernel_launch(void* const* d_in, const int* in_sizes, int n_in,
                              void* d_out, int out_size) {
    const float* logits = (const float*)d_in[0];   // [B,Q,81]
    const float* pboxes = (const float*)d_in[1];   // [B,Q,5]
    const float* tboxes = (const float*)d_in[2];   // [B,M,5]
    const float* sizes  = (const float*)d_in[3];   // [B,2]
    const int*   labels = (const int*)d_in[4];     // [B,M]
    float* out = (float*)d_out;

    // A: 28800 warps, 8 warps/block
    k_softmax_stats<<<(BB * QQ + 7) / 8, 256>>>(logits);
    // B: grid (Q/QT, B), block M
    dim3 gb(QQ / QT, BB);
    k_cost<<<gb, MM>>>(logits, pboxes, tboxes, sizes, labels);
    // C: one block per image
    k_match<<<BB, 256>>>();
    // D: per-image losses
    k_loss<<<BB, 256>>>(logits, pboxes, tboxes, sizes, labels);
    // E: final mean
    k_final<<<1, 32>>>(out);
}

// round 2
// speedup vs baseline: 4.3606x; 4.3606x over previous
#include <cuda_runtime.h>
#include <math.h>
#include <float.h>

#define BB 32
#define QQ 900
#define MM 128
#define KC 80
#define KP1 81
#define QT 4

#define INFF __int_as_float(0x7f800000)

// scratch (no allocations allowed -> __device__ globals)
__device__ float g_cost[BB * QQ * MM];      // 14.7 MB
__device__ float g_prob[BB * QQ * KP1];     // 9.3 MB softmax probs
__device__ float g_lse[BB * QQ];            // logsumexp
__device__ float g_psc[BB * QQ * 2];        // cos/sin of pred theta
__device__ int   g_qidx[BB * MM];
__device__ int   g_midx[BB * MM];
__device__ float g_il[BB * 3];

// ---------------- kernel A: per-(b,q) softmax probs + lse + sincos -------------
__global__ void k_prep(const float* __restrict__ logits,
                       const float* __restrict__ pboxes) {
    int warp = (blockIdx.x * blockDim.x + threadIdx.x) >> 5;
    int lane = threadIdx.x & 31;
    if (warp >= BB * QQ) return;
    const float* row = logits + (size_t)warp * KP1;
    float x0 = (lane      < KP1) ? row[lane]      : -FLT_MAX;
    float x1 = (lane + 32 < KP1) ? row[lane + 32] : -FLT_MAX;
    float x2 = (lane + 64 < KP1) ? row[lane + 64] : -FLT_MAX;
    float mx = fmaxf(x0, fmaxf(x1, x2));
    for (int o = 16; o; o >>= 1) mx = fmaxf(mx, __shfl_xor_sync(0xffffffffu, mx, o));
    float e0 = (lane      < KP1) ? expf(x0 - mx) : 0.f;
    float e1 = (lane + 32 < KP1) ? expf(x1 - mx) : 0.f;
    float e2 = (lane + 64 < KP1) ? expf(x2 - mx) : 0.f;
    float s = e0 + e1 + e2;
    for (int o = 16; o; o >>= 1) s += __shfl_xor_sync(0xffffffffu, s, o);
    float inv = 1.f / s;
    float* pr = g_prob + (size_t)warp * KP1;
    if (lane      < KP1) pr[lane]      = e0 * inv;
    if (lane + 32 < KP1) pr[lane + 32] = e1 * inv;
    if (lane + 64 < KP1) pr[lane + 64] = e2 * inv;
    if (lane == 0) {
        g_lse[warp] = mx + logf(s);
        float th = pboxes[(size_t)warp * 5 + 4];
        float sn, cs;
        sincosf(th, &sn, &cs);
        g_psc[warp * 2 + 0] = cs;
        g_psc[warp * 2 + 1] = sn;
    }
}

// ---------------- kernel B: cost matrix [B,Q,M] -------------------------------
__global__ void k_cost(const float* __restrict__ pboxes,
                       const float* __restrict__ tboxes,
                       const float* __restrict__ sizes,
                       const int*   __restrict__ labels) {
    int b = blockIdx.y;
    int m = threadIdx.x;                     // blockDim.x == MM
    __shared__ float tn0[MM], tn1[MM], tn2[MM], tn3[MM], tc[MM], ts[MM];
    __shared__ int   tl[MM];
    float H = sizes[b * 2 + 0], W = sizes[b * 2 + 1];
    {
        const float* tb = tboxes + ((size_t)b * MM + m) * 5;
        tn0[m] = tb[0] / W; tn1[m] = tb[1] / H;
        tn2[m] = tb[2] / W; tn3[m] = tb[3] / H;
        float sn, cs;
        sincosf(tb[4], &sn, &cs);
        tc[m] = cs; ts[m] = sn;
        tl[m] = labels[b * MM + m];
    }
    __syncthreads();
    int q0 = blockIdx.x * QT;
#pragma unroll
    for (int qq = 0; qq < QT; qq++) {
        int q = q0 + qq;
        int row = b * QQ + q;
        const float* pb = pboxes + (size_t)row * 5;
        float p0 = pb[0], p1 = pb[1], p2 = pb[2], p3 = pb[3];
        float pc = g_psc[row * 2 + 0], ps = g_psc[row * 2 + 1];
        float prob = g_prob[(size_t)row * KP1 + tl[m]];
        float l1 = fabsf(p0 - tn0[m]) + fabsf(p1 - tn1[m]) +
                   fabsf(p2 - tn2[m]) + fabsf(p3 - tn3[m]);
        float cosd = pc * tc[m] + ps * ts[m];            // cos(p4 - t4)
        g_cost[(size_t)row * MM + m] = -2.f * prob + 5.f * l1 + 2.f * (1.f - cosd);
    }
}

// ---------------- kernel C: greedy matching, one block per image ---------------
// rowmin cache + masked warp-cooperative rescans. Tie-breaks replicate the
// flattened argmin (smallest q, then smallest m).
__global__ void __launch_bounds__(256, 1) k_match() {
    int b = blockIdx.x;
    int tid = threadIdx.x;
    int lane = tid & 31, wid = tid >> 5;
    __shared__ float rmin[QQ];
    __shared__ int   rarg[QQ];
    __shared__ float msk[MM];          // 0 for free column, +INF for used
    __shared__ float sv[8];
    __shared__ int   si[8];
    __shared__ int   s_selm, s_cnt;
    __shared__ short queue[QQ];
    const float* C = g_cost + (size_t)b * QQ * MM;

    for (int m = tid; m < MM; m += 256) msk[m] = 0.f;
    if (tid == 0) s_cnt = 0;

    // initial per-row minima (vectorized, 4 parallel compare chains)
    for (int q = tid; q < QQ; q += 256) {
        const float4* row = (const float4*)(C + (size_t)q * MM);
        float bx = INFF, by = INFF, bz = INFF, bw = INFF;
        int   ix = 0, iy = 0, iz = 0, iw = 0;
#pragma unroll
        for (int j = 0; j < 32; j++) {
            float4 v = row[j];
            if (v.x < bx) { bx = v.x; ix = 4 * j;     }
            if (v.y < by) { by = v.y; iy = 4 * j + 1; }
            if (v.z < bz) { bz = v.z; iz = 4 * j + 2; }
            if (v.w < bw) { bw = v.w; iw = 4 * j + 3; }
        }
        float bv = bx; int bm = ix;
        if (by < bv || (by == bv && iy < bm)) { bv = by; bm = iy; }
        if (bz < bv || (bz == bv && iz < bm)) { bv = bz; bm = iz; }
        if (bw < bv || (bw == bv && iw < bm)) { bv = bw; bm = iw; }
        rmin[q] = bv; rarg[q] = bm;
    }
    __syncthreads();

    for (int it = 0; it < MM; it++) {
        // --- phase 1: global argmin over rmin (value, then smallest q) ---
        float bv = INFF; int bq = -1;
        for (int q = tid; q < QQ; q += 256) {
            float v = rmin[q];
            if (v < bv) { bv = v; bq = q; }            // ascending q: keeps smallest
        }
        for (int o = 16; o; o >>= 1) {
            float vv = __shfl_down_sync(0xffffffffu, bv, o);
            int   qq = __shfl_down_sync(0xffffffffu, bq, o);
            if (vv < bv || (vv == bv && (unsigned)qq < (unsigned)bq)) { bv = vv; bq = qq; }
        }
        if (lane == 0) { sv[wid] = bv; si[wid] = bq; }
        __syncthreads();
        if (tid == 0) {
            float fv = sv[0]; int fq = si[0];
#pragma unroll
            for (int w = 1; w < 8; w++)
                if (sv[w] < fv || (sv[w] == fv && (unsigned)si[w] < (unsigned)fq)) {
                    fv = sv[w]; fq = si[w];
                }
            int mm = rarg[fq];
            s_selm = mm;
            g_qidx[b * MM + it] = fq;
            g_midx[b * MM + it] = mm;
            msk[mm] = INFF;
            rmin[fq] = INFF;
            rarg[fq] = -1;
            s_cnt = 0;
        }
        __syncthreads();
        if (it == MM - 1) break;

        // --- phase 2: collect rows whose cached argmin was consumed ---
        int mm = s_selm;
        for (int q = tid; q < QQ; q += 256)
            if (rarg[q] == mm) { int p = atomicAdd(&s_cnt, 1); queue[p] = (short)q; }
        __syncthreads();

        // --- phase 3: warp-cooperative rescans (branchless masked loads) ---
        int cnt = s_cnt;
        for (int i = wid; i < cnt; i += 8) {
            int q = queue[i];
            const float* row = C + (size_t)q * MM;
            float v0 = row[lane]      + msk[lane];
            float v1 = row[lane + 32] + msk[lane + 32];
            float v2 = row[lane + 64] + msk[lane + 64];
            float v3 = row[lane + 96] + msk[lane + 96];
            float nv = v0; int nm = lane;
            if (v1 < nv) { nv = v1; nm = lane + 32; }
            if (v2 < nv) { nv = v2; nm = lane + 64; }
            if (v3 < nv) { nv = v3; nm = lane + 96; }
            for (int o = 16; o; o >>= 1) {
                float vv = __shfl_down_sync(0xffffffffu, nv, o);
                int   cc = __shfl_down_sync(0xffffffffu, nm, o);
                if (vv < nv || (vv == nv && cc < nm)) { nv = vv; nm = cc; }
            }
            if (lane == 0) { rmin[q] = nv; rarg[q] = nm; }
        }
        __syncthreads();
    }
}

// ---------------- kernel D: per-image losses -----------------------------------
__device__ __forceinline__ float block_sum256(float v, float* buf) {
    int tid = threadIdx.x;
    buf[tid] = v;
    __syncthreads();
    for (int s = 128; s > 0; s >>= 1) {
        if (tid < s) buf[tid] += buf[tid + s];
        __syncthreads();
    }
    float r = buf[0];
    __syncthreads();
    return r;
}

__global__ void k_loss(const float* __restrict__ logits,
                       const float* __restrict__ pboxes,
                       const float* __restrict__ tboxes,
                       const float* __restrict__ sizes,
                       const int*   __restrict__ labels) {
    int b = blockIdx.x;
    int tid = threadIdx.x;                    // 256
    __shared__ int   mlab[QQ];
    __shared__ float buf[256];

    for (int q = tid; q < QQ; q += 256) mlab[q] = -1;
    __syncthreads();
    if (tid < MM) {
        int q = g_qidx[b * MM + tid];
        int m = g_midx[b * MM + tid];
        mlab[q] = labels[b * MM + m];
    }
    __syncthreads();

    float H = sizes[b * 2 + 0], W = sizes[b * 2 + 1];

    float sb = 0.f, sa = 0.f;
    if (tid < MM) {
        int q = g_qidx[b * MM + tid];
        int m = g_midx[b * MM + tid];
        const float* pb = pboxes + ((size_t)b * QQ + q) * 5;
        const float* tb = tboxes + ((size_t)b * MM + m) * 5;
        float n0 = tb[0] / W, n1 = tb[1] / H, n2 = tb[2] / W, n3 = tb[3] / H;
        sb = fabsf(pb[0] - n0) + fabsf(pb[1] - n1) +
             fabsf(pb[2] - n2) + fabsf(pb[3] - n3);
        sa = 1.f - cosf(pb[4] - tb[4]);
    }

    float num = 0.f, den = 0.f;
    for (int q = tid; q < QQ; q += 256) {
        int c = mlab[q];
        float w;
        if (c < 0) { c = KC; w = 0.1f; } else { w = 1.f; }
        int row = b * QQ + q;
        float lg = logits[(size_t)row * KP1 + c];
        float nll = g_lse[row] - lg;
        num += w * nll;
        den += w;
    }

    float sb_t  = block_sum256(sb, buf);
    float sa_t  = block_sum256(sa, buf);
    float num_t = block_sum256(num, buf);
    float den_t = block_sum256(den, buf);

    if (tid == 0) {
        g_il[b * 3 + 0] = num_t / den_t;
        g_il[b * 3 + 1] = sb_t / (float)(MM * 4) * 5.f;
        g_il[b * 3 + 2] = sa_t / (float)MM * 2.f;
    }
}

// ---------------- kernel E: batch mean -> 4 outputs ----------------------------
__global__ void k_final(float* __restrict__ out) {
    int b = threadIdx.x;                      // 32 threads
    float lc = g_il[b * 3 + 0];
    float lb = g_il[b * 3 + 1];
    float la = g_il[b * 3 + 2];
    for (int o = 16; o; o >>= 1) {
        lc += __shfl_xor_sync(0xffffffffu, lc, o);
        lb += __shfl_xor_sync(0xffffffffu, lb, o);
        la += __shfl_xor_sync(0xffffffffu, la, o);
    }
    if (b == 0) {
        lc /= (float)BB; lb /= (float)BB; la /= (float)BB;
        out[0] = lc;
        out[1] = lb;
        out[2] = la;
        out[3] = lc + lb + la;
    }
}

extern "C" void kernel_launch(void* const* d_in, const int* in_sizes, int n_in,
                              void* d_out, int out_size) {
    const float* logits = (const float*)d_in[0];   // [B,Q,81]
    const float* pboxes = (const float*)d_in[1];   // [B,Q,5]
    const float* tboxes = (const float*)d_in[2];   // [B,M,5]
    const float* sizes  = (const float*)d_in[3];   // [B,2]
    const int*   labels = (const int*)d_in[4];     // [B,M]
    float* out = (float*)d_out;

    k_prep<<<(BB * QQ + 7) / 8, 256>>>(logits, pboxes);
    dim3 gb(QQ / QT, BB);
    k_cost<<<gb, MM>>>(pboxes, tboxes, sizes, labels);
    k_match<<<BB, 256>>>();
    k_loss<<<BB, 256>>>(logits, pboxes, tboxes, sizes, labels);
    k_final<<<1, 32>>>(out);
}

// round 3
// speedup vs baseline: 16.9891x; 3.8960x over previous
#include <cuda_runtime.h>
#include <math.h>
#include <float.h>

#define BB 32
#define QQ 900
#define MM 128
#define KC 80
#define KP1 81
#define INFF __int_as_float(0x7f800000)

// scratch (no allocations allowed -> __device__ globals)
__device__ float g_costT[BB * MM * QQ];     // 14.7 MB, TRANSPOSED [b][m][q]
__device__ float g_lse[BB * QQ];
__device__ int   g_qidx[BB * MM];
__device__ int   g_midx[BB * MM];
__device__ float g_acc[3];

// monotone float->uint mapping (preserves < ordering)
__device__ __forceinline__ unsigned ford(float f) {
    unsigned u = __float_as_uint(f);
    return u ^ ((u >> 31) ? 0xffffffffu : 0x80000000u);
}

// ---------------- kernel A: fused softmax + transposed cost matrix -------------
// grid (8, B), block 128. Each block owns a 128-q tile of one image.
__global__ void __launch_bounds__(128) k_costT(
    const float* __restrict__ logits,
    const float* __restrict__ pboxes,
    const float* __restrict__ tboxes,
    const float* __restrict__ sizes,
    const int*   __restrict__ labels) {
    int b = blockIdx.y, tid = threadIdx.x;
    int q0 = blockIdx.x * 128;
    int q = q0 + tid;
    __shared__ float sprob[128 * KP1];       // 41.5 KB
    __shared__ float tn0[MM], tn1[MM], tn2[MM], tn3[MM], tc[MM], ts[MM];
    __shared__ int   tl[MM];

    if (b == 0 && blockIdx.x == 0 && tid < 3) g_acc[tid] = 0.f;

    float H = sizes[b * 2 + 0], W = sizes[b * 2 + 1];
    {   // tid doubles as target index m
        const float* tb = tboxes + ((size_t)b * MM + tid) * 5;
        tn0[tid] = tb[0] / W; tn1[tid] = tb[1] / H;
        tn2[tid] = tb[2] / W; tn3[tid] = tb[3] / H;
        float sn, cs; sincosf(tb[4], &sn, &cs);
        tc[tid] = cs; ts[tid] = sn;
        tl[tid] = labels[b * MM + tid];
    }
    // coalesced copy of this tile's logits into smem
    int nrow = min(128, QQ - q0);
    int tot = nrow * KP1;
    const float* lg0 = logits + ((size_t)b * QQ + q0) * KP1;
    for (int i = tid; i < tot; i += 128) sprob[i] = lg0[i];
    __syncthreads();

    bool valid = q < QQ;
    if (valid) {
        float* r = sprob + tid * KP1;        // stride 81: bank-conflict-free
        float mx = -FLT_MAX;
#pragma unroll 9
        for (int k = 0; k < KP1; k++) mx = fmaxf(mx, r[k]);
        float s = 0.f;
#pragma unroll 9
        for (int k = 0; k < KP1; k++) { float e = expf(r[k] - mx); r[k] = e; s += e; }
        float inv = 1.f / s;
#pragma unroll 9
        for (int k = 0; k < KP1; k++) r[k] *= inv;
        g_lse[b * QQ + q] = mx + logf(s);
    }
    __syncthreads();
    if (!valid) return;

    const float* pb = pboxes + ((size_t)b * QQ + q) * 5;
    float p0 = pb[0], p1 = pb[1], p2 = pb[2], p3 = pb[3];
    float ps, pc; sincosf(pb[4], &ps, &pc);
    const float* r = sprob + tid * KP1;
    float* outb = g_costT + (size_t)b * MM * QQ + q;
#pragma unroll 4
    for (int m = 0; m < MM; m++) {
        float prob = r[tl[m]];
        float l1 = fabsf(p0 - tn0[m]) + fabsf(p1 - tn1[m]) +
                   fabsf(p2 - tn2[m]) + fabsf(p3 - tn3[m]);
        float cosd = pc * tc[m] + ps * ts[m];            // cos(p4 - t4)
        outb[(size_t)m * QQ] = -2.f * prob + 5.f * l1 + 2.f * (1.f - cosd);
    }
}

// ---------------- kernel B: greedy matching, column-minima cache ---------------
// 8 warps init the 128 column minima; warp 0 alone runs the 128 iterations
// (no block barriers in the loop). Tie-breaks = flattened argmin (q, then m).
__global__ void __launch_bounds__(256, 1) k_match() {
    int b = blockIdx.x, tid = threadIdx.x;
    int lane = tid & 31, wid = tid >> 5;
    __shared__ float cmin[MM];
    __shared__ int   carg[MM];
    __shared__ float rmask[QQ];        // 0 = free row, +INF = used
    const float* C = g_costT + (size_t)b * MM * QQ;

    for (int q = tid; q < QQ; q += 256) rmask[q] = 0.f;

    // init: one warp per column (coalesced column scan)
    for (int m = wid; m < MM; m += 8) {
        const float* col = C + (size_t)m * QQ;
        float bv = INFF; int bq = -1;
#pragma unroll 7
        for (int j = 0; j < 28; j++) {
            int q = lane + 32 * j;
            float v = col[q];
            if (v < bv) { bv = v; bq = q; }            // ascending q keeps smallest
        }
        { int q = lane + 896; if (q < QQ) { float v = col[q]; if (v < bv) { bv = v; bq = q; } } }
        // warp reduce (value, then smallest q) via REDUX
        unsigned u = ford(bv);
        unsigned umin = __reduce_min_sync(0xffffffffu, u);
        unsigned qsel = (u == umin) ? (unsigned)bq : 0xffffffffu;
        unsigned qmin = __reduce_min_sync(0xffffffffu, qsel);
        if (lane == 0) { cmin[m] = bv; }               // value re-derived below
        if (lane == 0) { carg[m] = (int)qmin; cmin[m] = __uint_as_float(umin ^ ((umin >> 31) ? 0x80000000u : 0xffffffffu)); }
    }
    __syncthreads();
    if (wid != 0) return;

    int* qout = g_qidx + b * MM;
    int* mout = g_midx + b * MM;

    for (int it = 0; it < MM; it++) {
        // ---- global argmin over 128 column minima: 4 candidates per lane ----
        unsigned u[4]; int qm[4];
        unsigned long long key = ~0ull;
#pragma unroll
        for (int g = 0; g < 4; g++) {
            int m2 = lane + 32 * g;
            float v = cmin[m2];
            int q = carg[m2];
            u[g] = ford(v);
            qm[g] = q * 128 + m2;                       // 17-bit combined index
            unsigned long long k2 = ((unsigned long long)u[g] << 17) | (unsigned)qm[g];
            if (k2 < key) key = k2;
        }
        unsigned hi = (unsigned)(key >> 17);
        unsigned himin = __reduce_min_sync(0xffffffffu, hi);
        unsigned lo = (hi == himin) ? (unsigned)(key & 0x1ffffu) : 0xffffffffu;
        unsigned lomin = __reduce_min_sync(0xffffffffu, lo);
        int qs = (int)(lomin >> 7);
        int ms = (int)(lomin & 127u);

        if (lane == 0) {
            qout[it] = qs; mout[it] = ms;
            rmask[qs] = INFF;
            cmin[ms] = INFF;
            carg[ms] = 0x7fffffff;
        }
        __syncwarp();
        if (it == MM - 1) break;

        // ---- rescan columns whose cached argmin row was just consumed ----
#pragma unroll
        for (int g = 0; g < 4; g++) {
            int m2 = lane + 32 * g;
            int cq = qm[g] >> 7;                        // cached carg from load above
            unsigned bal = __ballot_sync(0xffffffffu, cq == qs && m2 != ms && u[g] != 0xffffffffu);
            while (bal) {
                int c = __ffs(bal) - 1; bal &= bal - 1;
                int mr = c + 32 * g;
                const float* col = C + (size_t)mr * QQ;
                float nv = INFF; int nq = -1;
#pragma unroll 7
                for (int j = 0; j < 28; j++) {
                    int q2 = lane + 32 * j;
                    float v = col[q2] + rmask[q2];
                    if (v < nv) { nv = v; nq = q2; }
                }
                { int q2 = lane + 896; if (q2 < QQ) { float v = col[q2] + rmask[q2]; if (v < nv) { nv = v; nq = q2; } } }
                unsigned uu = ford(nv);
                unsigned um = __reduce_min_sync(0xffffffffu, uu);
                unsigned qq = (uu == um) ? (unsigned)nq : 0xffffffffu;
                unsigned qmn = __reduce_min_sync(0xffffffffu, qq);
                if (lane == 0) {
                    carg[mr] = (int)qmn;
                    cmin[mr] = __uint_as_float(um ^ ((um >> 31) ? 0x80000000u : 0xffffffffu));
                }
                __syncwarp();
            }
        }
    }
}

// ---------------- kernel C: losses (parallel over B x 4 q-chunks) --------------
__device__ __forceinline__ float block_sum256(float v, float* buf) {
    int tid = threadIdx.x;
    buf[tid] = v;
    __syncthreads();
    for (int s = 128; s > 0; s >>= 1) {
        if (tid < s) buf[tid] += buf[tid + s];
        __syncthreads();
    }
    float r = buf[0];
    __syncthreads();
    return r;
}

__global__ void k_loss(const float* __restrict__ logits,
                       const float* __restrict__ pboxes,
                       const float* __restrict__ tboxes,
                       const float* __restrict__ sizes,
                       const int*   __restrict__ labels) {
    int b = blockIdx.x, chunk = blockIdx.y, tid = threadIdx.x;  // block 256
    __shared__ int   mlab[QQ];
    __shared__ float buf[256];
    int qlo = chunk * 225, qhi = min(qlo + 225, QQ);

    for (int q = qlo + tid; q < qhi; q += 256) mlab[q] = -1;
    __syncthreads();
    if (tid < MM) {
        int q = g_qidx[b * MM + tid];
        if (q >= qlo && q < qhi) mlab[q] = labels[b * MM + g_midx[b * MM + tid]];
    }
    __syncthreads();

    float num = 0.f;
    for (int q = qlo + tid; q < qhi; q += 256) {
        int c = mlab[q];
        float w;
        if (c < 0) { c = KC; w = 0.1f; } else w = 1.f;
        int row = b * QQ + q;
        num += w * (g_lse[row] - logits[(size_t)row * KP1 + c]);
    }

    float sb = 0.f, sa = 0.f;
    if (chunk == 0 && tid < MM) {
        int q = g_qidx[b * MM + tid];
        int m = g_midx[b * MM + tid];
        float H = sizes[b * 2 + 0], W = sizes[b * 2 + 1];
        const float* pb = pboxes + ((size_t)b * QQ + q) * 5;
        const float* tb = tboxes + ((size_t)b * MM + m) * 5;
        sb = fabsf(pb[0] - tb[0] / W) + fabsf(pb[1] - tb[1] / H) +
             fabsf(pb[2] - tb[2] / W) + fabsf(pb[3] - tb[3] / H);
        sa = 1.f - cosf(pb[4] - tb[4]);
    }

    float numt = block_sum256(num, buf);
    if (tid == 0) atomicAdd(&g_acc[0], numt);
    if (chunk == 0) {
        float sbt = block_sum256(sb, buf);
        float sat = block_sum256(sa, buf);
        if (tid == 0) { atomicAdd(&g_acc[1], sbt); atomicAdd(&g_acc[2], sat); }
    }
}

// ---------------- kernel D: final scalars --------------------------------------
__global__ void k_final(float* __restrict__ out) {
    if (threadIdx.x == 0) {
        const float den = 0.1f * (QQ - MM) + (float)MM;   // 205.2 per image
        float lc = g_acc[0] / (den * BB);
        float lb = g_acc[1] * 5.f / (float)(MM * 4 * BB);
        float la = g_acc[2] * 2.f / (float)(MM * BB);
        out[0] = lc;
        out[1] = lb;
        out[2] = la;
        out[3] = lc + lb + la;
    }
}

extern "C" void kernel_launch(void* const* d_in, const int* in_sizes, int n_in,
                              void* d_out, int out_size) {
    const float* logits = (const float*)d_in[0];   // [B,Q,81]
    const float* pboxes = (const float*)d_in[1];   // [B,Q,5]
    const float* tboxes = (const float*)d_in[2];   // [B,M,5]
    const float* sizes  = (const float*)d_in[3];   // [B,2]
    const int*   labels = (const int*)d_in[4];     // [B,M]
    float* out = (float*)d_out;

    dim3 gc((QQ + 127) / 128, BB);
    k_costT<<<gc, 128>>>(logits, pboxes, tboxes, sizes, labels);
    k_match<<<BB, 256>>>();
    dim3 gl(BB, 4);
    k_loss<<<gl, 256>>>(logits, pboxes, tboxes, sizes, labels);
    k_final<<<1, 32>>>(out);
}